// round 15
// baseline (speedup 1.0000x reference)
#include <cuda_runtime.h>
#include <cstdint>

// Problem constants (shapes fixed by the dataset)
#define NN 65536
#define EE 262144

// Scratch (static __device__ arrays; allocation APIs are forbidden)
__device__ float g_XA[(size_t)NN * 512];
__device__ float g_XB[(size_t)NN * 512];
__device__ float g_AG[(size_t)NN * 512];
__device__ float g_WT[1482752];  // transposed+rounded+k-permuted weights [N][K]
__device__ float g_WFP[512];     // permuted Wf
__device__ float g_LNS[512];     // 2 buffers x 128 segs x {s1,s2}
__device__ int   g_CNT[NN];
__device__ int   g_OFF[NN + 1];
__device__ int   g_TOPS[64];
__device__ int   g_ADJ[EE];

// offsets into g_WT (floats)
#define T_W1 0          // [384 n][192 k]
#define T_W2 73728      // [256 n][384 k]
#define T_S0 172032     // [512 n][512 k]   = Wl0^T | Wr0^T
#define T_S1 434176     // [512 n][1024 k]  = Wl1^T | Wr1^T
#define T_S2 958464     // [512 n][1024 k]  = Wl2^T | Wr2^T

__device__ __forceinline__ float rnd_tf32(float x) {
    uint32_t u;
    asm("cvt.rna.tf32.f32 %0, %1;" : "=r"(u) : "f"(x));
    return __uint_as_float(u);
}

// 4x4 transpose permutation within each 16-block (involution)
__device__ __forceinline__ int perm16(int c) {
    return (c & ~15) | ((c & 3) << 2) | ((c >> 2) & 3);
}

// ---------------------------------------------------------------------------
__global__ void zero_int(int* p, int n) {
    int i = blockIdx.x * blockDim.x + threadIdx.x;
    if (i < n) p[i] = 0;
}
__global__ void zero_f(float* p, int n) {
    int i = blockIdx.x * blockDim.x + threadIdx.x;
    if (i < n) p[i] = 0.f;
}
__global__ void init_out(float* out, const float* bf, int n) {
    int i = blockIdx.x * blockDim.x + threadIdx.x;
    if (i < n) out[i] = bf[0];
}

// Transpose + tf32-round + k-permute:
// dst[n*ldk + kofs + p] = rnd(src[perm16(p)*N + n]), zero-padded.
__global__ void transpose_w(const float* __restrict__ src, float* __restrict__ dst,
                            int K, int N, int Kloop, int Nloop, int ldk, int kofs) {
    int i = blockIdx.x * blockDim.x + threadIdx.x;
    if (i >= Nloop * Kloop) return;
    int n = i / Kloop, p = i % Kloop;
    int k = perm16(p);
    dst[(size_t)n * ldk + kofs + p] = (k < K && n < N) ? rnd_tf32(src[(size_t)k * N + n]) : 0.f;
}

__global__ void permute_wf(const float* __restrict__ Wf, float* __restrict__ WfP) {
    int p = blockIdx.x * blockDim.x + threadIdx.x;
    if (p < 512) WfP[p] = Wf[perm16(p)];
}

// ---------------------------------------------------------------------------
// Build input features, stored k-permuted: position p holds logical feature perm16(p)
__global__ void build_x(const float* __restrict__ nf, const int* __restrict__ ncf,
                        const int* __restrict__ ops, const float* __restrict__ opemb,
                        const float* __restrict__ catemb, float* __restrict__ X) {
    int n = blockIdx.x;
    int p = threadIdx.x;
    if (p >= 192) return;
    int c = perm16(p);
    float v = 0.f;
    if (c < 16) {
        int f = c >> 2, e = c & 3;
        int cat = (int)nf[(size_t)n * 105 + 101 + f];
        v = catemb[cat * 4 + e];
    } else if (c < 24) {
        int f = (c - 16) >> 2, e = (c - 16) & 3;
        int cat = ncf[n * 2 + f];
        v = catemb[cat * 4 + e];
    } else if (c < 125) {
        v = nf[(size_t)n * 105 + (c - 24)];
    } else if (c < 189) {
        v = opemb[ops[n] * 64 + (c - 125)];
    }
    X[(size_t)n * 192 + p] = rnd_tf32(v);
}

// ---------------------------------------------------------------------------
// CSR build: histogram -> exclusive scan (64 x 1024) -> fill
__global__ void hist_dst(const int* __restrict__ dst, int* __restrict__ cnt, int E) {
    int i = blockIdx.x * blockDim.x + threadIdx.x;
    if (i < E) atomicAdd(&cnt[dst[i]], 1);
}

__global__ void scan1(const int* __restrict__ in, int* __restrict__ out, int* __restrict__ tops) {
    __shared__ int sh[1024];
    int t = threadIdx.x;
    int i = blockIdx.x * 1024 + t;
    int v = in[i];
    sh[t] = v;
    __syncthreads();
    for (int o = 1; o < 1024; o <<= 1) {
        int x = (t >= o) ? sh[t - o] : 0;
        __syncthreads();
        sh[t] += x;
        __syncthreads();
    }
    out[i] = sh[t] - v;
    if (t == 1023) tops[blockIdx.x] = sh[t];
}

__global__ void scan2(int* __restrict__ tops, int* __restrict__ off, int E) {
    __shared__ int sh[64];
    int t = threadIdx.x;
    int v = tops[t];
    sh[t] = v;
    __syncthreads();
    for (int o = 1; o < 64; o <<= 1) {
        int x = (t >= o) ? sh[t - o] : 0;
        __syncthreads();
        sh[t] += x;
        __syncthreads();
    }
    tops[t] = sh[t] - v;
    if (t == 0) off[NN] = E;
}

__global__ void scan3(int* __restrict__ out, const int* __restrict__ tops) {
    out[blockIdx.x * 1024 + threadIdx.x] += tops[blockIdx.x];
}

__global__ void fill_adj(const int* __restrict__ src, const int* __restrict__ dst,
                         const int* __restrict__ off, int* __restrict__ cnt,
                         int* __restrict__ adj, int E) {
    int i = blockIdx.x * blockDim.x + threadIdx.x;
    if (i >= E) return;
    int d = dst[i];
    int p = off[d] + atomicAdd(&cnt[d], 1);
    adj[p] = src[i];
}

// ---------------------------------------------------------------------------
// CSR mean-aggregation (positionally blind -> permutation-safe)
template <int NQ>
__global__ void aggregate(const float4* __restrict__ X, const int* __restrict__ off,
                          const int* __restrict__ adj, float4* __restrict__ AG) {
    int row = (blockIdx.x * blockDim.x + threadIdx.x) >> 5;
    int lane = threadIdx.x & 31;
    if (row >= NN) return;
    int s0 = off[row], s1 = off[row + 1];
    float4 acc[NQ];
#pragma unroll
    for (int q = 0; q < NQ; q++) acc[q] = make_float4(0.f, 0.f, 0.f, 0.f);
    for (int e = s0; e < s1; e++) {
        int s = adj[e];
        const float4* xr = X + (size_t)s * (NQ * 32);
#pragma unroll
        for (int q = 0; q < NQ; q++) {
            float4 v = xr[lane + 32 * q];
            acc[q].x += v.x; acc[q].y += v.y; acc[q].z += v.z; acc[q].w += v.w;
        }
    }
    float inv = 1.0f / fmaxf((float)(s1 - s0), 1.0f);
    float4* o = AG + (size_t)row * (NQ * 32);
#pragma unroll
    for (int q = 0; q < NQ; q++) {
        float4 u;
        u.x = rnd_tf32(acc[q].x * inv);
        u.y = rnd_tf32(acc[q].y * inv);
        u.z = rnd_tf32(acc[q].z * inv);
        u.w = rnd_tf32(acc[q].w * inv);
        o[lane + 32 * q] = u;
    }
}

// ---------------------------------------------------------------------------
// tf32 tensor-core GEMM, k-permuted layout, minimal-load schedule:
// warp tile 32x64 (wm 4 groups, wn 2 groups). A fragments (4 uint4) cached
// across the k-tile; B streamed one uint4 per 8-col group.
// Per warp per 16-K tile: 12 LDS.128 + 32 MMA.
#define STAGES 4
#define MAT_WORDS (128 * 16)
#define STAGE_WORDS (2 * MAT_WORDS)
#define SMEM_WORDS (STAGES * STAGE_WORDS)   // 16384 words = 64KB

__device__ __forceinline__ void cpa16(void* smem, const void* gmem) {
    uint32_t s = (uint32_t)__cvta_generic_to_shared(smem);
    asm volatile("cp.async.cg.shared.global [%0], [%1], 16;" :: "r"(s), "l"(gmem) : "memory");
}

__device__ __forceinline__ void mma_tf32(float* c, uint32_t a0, uint32_t a1,
                                         uint32_t a2, uint32_t a3,
                                         uint32_t b0, uint32_t b1) {
    asm volatile(
        "mma.sync.aligned.m16n8k8.row.col.f32.tf32.tf32.f32 "
        "{%0,%1,%2,%3}, {%4,%5,%6,%7}, {%8,%9}, {%0,%1,%2,%3};"
        : "+f"(c[0]), "+f"(c[1]), "+f"(c[2]), "+f"(c[3])
        : "r"(a0), "r"(a1), "r"(a2), "r"(a3), "r"(b0), "r"(b1));
}

__global__ void __launch_bounds__(256, 2)
gemm_tc(const float* __restrict__ A1, const float* __restrict__ A2, int lda, int Mk1,
        const float* __restrict__ WT, const float* __restrict__ bias,
        float* __restrict__ C, int ldc,
        int Ktot, int Kbias, int act, float* segsum, int rps) {
    extern __shared__ uint32_t dynsmem[];

    const int tid = threadIdx.x;
    const int wid = tid >> 5, lane = tid & 31;
    const int wm = wid & 3, wn = wid >> 2;   // 4 m-groups x 2 n-groups
    const int g = lane >> 2, t4 = lane & 3;
    const int row0 = blockIdx.y * 128;
    const int col0 = blockIdx.x * 128;
    const int T = Ktot >> 4;

    float acc[2][8][4];
#pragma unroll
    for (int i = 0; i < 2; i++)
#pragma unroll
        for (int j = 0; j < 8; j++)
#pragma unroll
            for (int r = 0; r < 4; r++) acc[i][j][r] = 0.f;

    auto issue = [&](int t) {
        int st = t % STAGES;
        int k0 = t << 4;
        const float* Ap = (k0 < Mk1) ? A1 + k0 : A2 + (k0 - Mk1);
        const float* Bp = WT + k0;
        uint32_t* As = dynsmem + st * STAGE_WORDS;
        uint32_t* Bs = As + MAT_WORDS;
#pragma unroll
        for (int it = 0; it < 2; it++) {
            int f = tid + it * 256;
            int r = f >> 2, q = (f & 3) << 2;
            cpa16(&As[r * 16 + q], Ap + (size_t)(row0 + r) * lda + q);
            cpa16(&Bs[r * 16 + q], Bp + (size_t)(col0 + r) * Ktot + q);
        }
        asm volatile("cp.async.commit_group;" ::: "memory");
    };

    issue(0);
    if (T > 1) issue(1);
    if (T > 2) issue(2);
    for (int t = 0; t < T; t++) {
        int rem = T - 1 - t;
        if (rem >= 2)      asm volatile("cp.async.wait_group 2;" ::: "memory");
        else if (rem == 1) asm volatile("cp.async.wait_group 1;" ::: "memory");
        else               asm volatile("cp.async.wait_group 0;" ::: "memory");
        __syncthreads();
        if (t + 3 < T) issue(t + 3);
        int st = t % STAGES;
        const uint32_t* As = dynsmem + st * STAGE_WORDS;
        const uint32_t* Bs = As + MAT_WORDS;

        // cache A fragments (4 uint4 = 16 regs), stream B
        uint4 qa[2][2];
#pragma unroll
        for (int i = 0; i < 2; i++) {
            int m = wm * 32 + i * 16 + g;
            qa[i][0] = *(const uint4*)&As[m * 16 + 4 * t4];
            qa[i][1] = *(const uint4*)&As[(m + 8) * 16 + 4 * t4];
        }
#pragma unroll
        for (int j = 0; j < 8; j++) {
            uint4 qb = *(const uint4*)&Bs[(wn * 64 + j * 8 + g) * 16 + 4 * t4];
#pragma unroll
            for (int i = 0; i < 2; i++) {
                mma_tf32(acc[i][j], qa[i][0].x, qa[i][1].x, qa[i][0].y, qa[i][1].y,
                         qb.x, qb.y);
                mma_tf32(acc[i][j], qa[i][0].z, qa[i][1].z, qa[i][0].w, qa[i][1].w,
                         qb.z, qb.w);
            }
        }
    }
    __syncthreads();

    // epilogue: bias + act (+ LN stats); store to k-permuted positions
    float ts1 = 0.f, ts2 = 0.f;
#pragma unroll
    for (int i = 0; i < 2; i++) {
        int m = row0 + wm * 32 + i * 16 + g;
#pragma unroll
        for (int j = 0; j < 8; j++) {
            int n = col0 + wn * 64 + j * 8 + t4 * 2;   // logical (even)
            int pn = perm16(n);                        // perm16(n+1) == pn + 4
            float b0 = (n < Kbias) ? bias[n] : 0.f;
            float b1v = (n + 1 < Kbias) ? bias[n + 1] : 0.f;
            float v0 = acc[i][j][0] + b0;
            float v1 = acc[i][j][1] + b1v;
            float v2 = acc[i][j][2] + b0;
            float v3 = acc[i][j][3] + b1v;
            if (act == 1) {
                v0 = v0 >= 0.f ? v0 : 0.01f * v0;
                v1 = v1 >= 0.f ? v1 : 0.01f * v1;
                v2 = v2 >= 0.f ? v2 : 0.01f * v2;
                v3 = v3 >= 0.f ? v3 : 0.01f * v3;
            }
            if (segsum) {
                ts1 += v0 + v1 + v2 + v3;
                ts2 += v0 * v0 + v1 * v1 + v2 * v2 + v3 * v3;
            }
            C[(size_t)m * ldc + pn] = v0;
            C[(size_t)m * ldc + pn + 4] = v1;
            C[(size_t)(m + 8) * ldc + pn] = v2;
            C[(size_t)(m + 8) * ldc + pn + 4] = v3;
        }
    }

    if (segsum) {
        __shared__ float red[256];
        red[tid] = ts1;
        __syncthreads();
        for (int o = 128; o > 0; o >>= 1) {
            if (tid < o) red[tid] += red[tid + o];
            __syncthreads();
        }
        if (tid == 0) atomicAdd(&segsum[(row0 / rps) * 2], red[0]);
        __syncthreads();
        red[tid] = ts2;
        __syncthreads();
        for (int o = 128; o > 0; o >>= 1) {
            if (tid < o) red[tid] += red[tid + o];
            __syncthreads();
        }
        if (tid == 0) atomicAdd(&segsum[(row0 / rps) * 2 + 1], red[0]);
    }
}

// ---------------------------------------------------------------------------
// Graph-wise LN apply; w/b loaded through perm16 so positional math is plain.
__global__ void graph_ln_apply(float4* __restrict__ X, const float* __restrict__ w,
                               const float* __restrict__ b, const float* __restrict__ segsum,
                               int F, int ld4, int rps) {
    __shared__ float sw[384], sb[384];
    int t = threadIdx.x;
    int cols = ld4 * 4;
    for (int p = t; p < cols; p += 512) {
        int lc = perm16(p);
        sw[p] = (lc < F) ? w[lc] : 0.f;
        sb[p] = (lc < F) ? b[lc] : 0.f;
    }
    __syncthreads();
    float cnt = (float)rps * (float)F;
    float mean = segsum[blockIdx.x * 2] / cnt;
    float var = segsum[blockIdx.x * 2 + 1] / cnt - mean * mean;
    float inv = rsqrtf(var + 1e-5f);
    size_t base = (size_t)blockIdx.x * rps * ld4;
    int total = rps * ld4;
    for (int i = t; i < total; i += 512) {
        float4 v = X[base + i];
        int c = (i % ld4) * 4;
        v.x = rnd_tf32((v.x - mean) * inv * sw[c + 0] + sb[c + 0]);
        v.y = rnd_tf32((v.y - mean) * inv * sw[c + 1] + sb[c + 1]);
        v.z = rnd_tf32((v.z - mean) * inv * sw[c + 2] + sb[c + 2]);
        v.w = rnd_tf32((v.w - mean) * inv * sw[c + 3] + sb[c + 3]);
        X[base + i] = v;
    }
}

// ---------------------------------------------------------------------------
// Row L2 normalize (512 cols) + relu + tf32 round. Permutation-invariant.
__global__ void row_l2norm(float4* __restrict__ X, int nrows) {
    int warp = (blockIdx.x * blockDim.x + threadIdx.x) >> 5;
    int lane = threadIdx.x & 31;
    if (warp >= nrows) return;
    float4* row = X + (size_t)warp * 128;
    float4 v[4];
    float ss = 0.f;
#pragma unroll
    for (int k = 0; k < 4; k++) {
        v[k] = row[lane + 32 * k];
        ss += v[k].x * v[k].x + v[k].y * v[k].y + v[k].z * v[k].z + v[k].w * v[k].w;
    }
#pragma unroll
    for (int o = 16; o > 0; o >>= 1) ss += __shfl_xor_sync(0xffffffff, ss, o);
    float s = 1.0f / fmaxf(sqrtf(ss), 1e-12f);
#pragma unroll
    for (int k = 0; k < 4; k++) {
        float4 u = v[k];
        u.x = rnd_tf32(fmaxf(u.x * s, 0.f));
        u.y = rnd_tf32(fmaxf(u.y * s, 0.f));
        u.z = rnd_tf32(fmaxf(u.z * s, 0.f));
        u.w = rnd_tf32(fmaxf(u.w * s, 0.f));
        row[lane + 32 * k] = u;
    }
}

// ---------------------------------------------------------------------------
// Fused last layer: l2-normalize row, dot with permuted Wf, atomicAdd out[seg].
__global__ void l2norm_final(const float4* __restrict__ X, const float* __restrict__ WfP,
                             float* __restrict__ out, int nrows, int rps) {
    int warp = (blockIdx.x * blockDim.x + threadIdx.x) >> 5;
    int lane = threadIdx.x & 31;
    if (warp >= nrows) return;
    const float4* row = X + (size_t)warp * 128;
    const float4* wf4 = (const float4*)WfP;
    float ss = 0.f, dot = 0.f;
#pragma unroll
    for (int k = 0; k < 4; k++) {
        float4 v = row[lane + 32 * k];
        float4 w = wf4[lane + 32 * k];
        ss += v.x * v.x + v.y * v.y + v.z * v.z + v.w * v.w;
        dot += v.x * w.x + v.y * w.y + v.z * w.z + v.w * w.w;
    }
#pragma unroll
    for (int o = 16; o > 0; o >>= 1) {
        ss += __shfl_xor_sync(0xffffffff, ss, o);
        dot += __shfl_xor_sync(0xffffffff, dot, o);
    }
    if (lane == 0) {
        float s = 1.0f / fmaxf(sqrtf(ss), 1e-12f);
        atomicAdd(&out[warp / rps], dot * s);
    }
}

// ---------------------------------------------------------------------------
extern "C" void kernel_launch(void* const* d_in, const int* in_sizes, int n_in,
                              void* d_out, int out_size) {
    const float* nf    = (const float*)d_in[0];
    const int*   ncf   = (const int*)d_in[1];
    const int*   ops   = (const int*)d_in[3];
    const int*   edges = (const int*)d_in[4];
    const float* opemb = (const float*)d_in[6];
    const float* catemb= (const float*)d_in[7];
    const float* W1    = (const float*)d_in[8];
    const float* b1    = (const float*)d_in[9];
    const float* ln1w  = (const float*)d_in[10];
    const float* ln1b  = (const float*)d_in[11];
    const float* W2    = (const float*)d_in[12];
    const float* b2    = (const float*)d_in[13];
    const float* ln2w  = (const float*)d_in[14];
    const float* ln2b  = (const float*)d_in[15];
    const float* Wl0   = (const float*)d_in[16];
    const float* bl0   = (const float*)d_in[17];
    const float* Wr0   = (const float*)d_in[18];
    const float* Wl1   = (const float*)d_in[19];
    const float* bl1   = (const float*)d_in[20];
    const float* Wr1   = (const float*)d_in[21];
    const float* Wl2   = (const float*)d_in[22];
    const float* bl2   = (const float*)d_in[23];
    const float* Wr2   = (const float*)d_in[24];
    const float* Wf    = (const float*)d_in[25];
    const float* bfp   = (const float*)d_in[26];
    float* out = (float*)d_out;

    const int N = in_sizes[3];
    const int S = in_sizes[2];
    const int E = in_sizes[4] / 2;
    const int rps = N / S;
    const int* esrc = edges;
    const int* edst = edges + E;

    float *XA, *XB, *AG, *WT, *WFP, *LNS;
    int *CNT, *OFF, *TOPS, *ADJ;
    cudaGetSymbolAddress((void**)&XA, g_XA);
    cudaGetSymbolAddress((void**)&XB, g_XB);
    cudaGetSymbolAddress((void**)&AG, g_AG);
    cudaGetSymbolAddress((void**)&WT, g_WT);
    cudaGetSymbolAddress((void**)&WFP, g_WFP);
    cudaGetSymbolAddress((void**)&LNS, g_LNS);
    cudaGetSymbolAddress((void**)&CNT, g_CNT);
    cudaGetSymbolAddress((void**)&OFF, g_OFF);
    cudaGetSymbolAddress((void**)&TOPS, g_TOPS);
    cudaGetSymbolAddress((void**)&ADJ, g_ADJ);

    const int gy = N / 128;
    const int smem_bytes = SMEM_WORDS * 4;   // 65536
    cudaFuncSetAttribute(gemm_tc, cudaFuncAttributeMaxDynamicSharedMemorySize, smem_bytes);

    // 1. W1 transpose (needed by GEMM1 at launch #4)
    transpose_w<<<(384 * 192 + 255) / 256, 256>>>(W1, WT + T_W1, 189, 378, 192, 384, 192, 0);
    // 2. zero LN stats
    zero_f<<<2, 256>>>(LNS, 512);
    // 3. feature assembly (permuted) -> AG used as X1 [N,192]
    build_x<<<N, 192>>>(nf, ncf, ops, opemb, catemb, AG);
    // 4. XB = LN-stats(leaky(X1 @ W1 + b1))  [N,378 perm @ stride 384]  << profiled
    gemm_tc<<<dim3(3, gy), 256, smem_bytes>>>(AG, AG, 192, 192, WT + T_W1, b1, XB, 384,
                                              192, 378, 1, LNS, rps);
    // 5. LN apply
    graph_ln_apply<<<S, 512>>>((float4*)XB, ln1w, ln1b, LNS, 378, 96, rps);
    // 6. remaining weight transposes + Wf permute
    transpose_w<<<(256 * 384 + 255) / 256, 256>>>(W2, WT + T_W2, 378, 256, 384, 256, 384, 0);
    transpose_w<<<(512 * 256 + 255) / 256, 256>>>(Wl0, WT + T_S0, 256, 512, 256, 512, 512, 0);
    transpose_w<<<(512 * 256 + 255) / 256, 256>>>(Wr0, WT + T_S0, 256, 512, 256, 512, 512, 256);
    transpose_w<<<(512 * 512 + 255) / 256, 256>>>(Wl1, WT + T_S1, 512, 512, 512, 512, 1024, 0);
    transpose_w<<<(512 * 512 + 255) / 256, 256>>>(Wr1, WT + T_S1, 512, 512, 512, 512, 1024, 512);
    transpose_w<<<(512 * 512 + 255) / 256, 256>>>(Wl2, WT + T_S2, 512, 512, 512, 512, 1024, 0);
    transpose_w<<<(512 * 512 + 255) / 256, 256>>>(Wr2, WT + T_S2, 512, 512, 512, 512, 1024, 512);
    permute_wf<<<2, 256>>>(Wf, WFP);

    // 7. XA = LN(leaky(XB @ W2 + b2))  [N,256]; stats fused
    gemm_tc<<<dim3(2, gy), 256, smem_bytes>>>(XB, XB, 384, 384, WT + T_W2, b2, XA, 256,
                                              384, 256, 1, LNS + 256, rps);
    graph_ln_apply<<<S, 512>>>((float4*)XA, ln2w, ln2b, LNS + 256, 256, 64, rps);

    // CSR build (needed before first aggregate)
    zero_int<<<N / 256, 256>>>(CNT, N);
    hist_dst<<<(E + 255) / 256, 256>>>(edst, CNT, E);
    scan1<<<64, 1024>>>(CNT, OFF, TOPS);
    scan2<<<1, 64>>>(TOPS, OFF, E);
    scan3<<<64, 1024>>>(OFF, TOPS);
    zero_int<<<N / 256, 256>>>(CNT, N);
    fill_adj<<<(E + 255) / 256, 256>>>(esrc, edst, OFF, CNT, ADJ, E);

    // SAGE layer 0: 256 -> 512, relu(l2norm)
    aggregate<2><<<N / 8, 256>>>((const float4*)XA, OFF, ADJ, (float4*)AG);
    gemm_tc<<<dim3(4, gy), 256, smem_bytes>>>(AG, XA, 256, 256, WT + T_S0, bl0, XB, 512,
                                              512, 512, 0, nullptr, rps);
    row_l2norm<<<(N + 7) / 8, 256>>>((float4*)XB, N);

    // SAGE layer 1: 512 -> 512, relu(l2norm)
    aggregate<4><<<N / 8, 256>>>((const float4*)XB, OFF, ADJ, (float4*)AG);
    gemm_tc<<<dim3(4, gy), 256, smem_bytes>>>(AG, XB, 512, 512, WT + T_S1, bl1, XA, 512,
                                              1024, 512, 0, nullptr, rps);
    row_l2norm<<<(N + 7) / 8, 256>>>((float4*)XA, N);

    // SAGE layer 2: 512 -> 512, fused l2norm+dot+segment-reduce
    aggregate<4><<<N / 8, 256>>>((const float4*)XA, OFF, ADJ, (float4*)AG);
    gemm_tc<<<dim3(4, gy), 256, smem_bytes>>>(AG, XA, 512, 512, WT + T_S2, bl2, XB, 512,
                                              1024, 512, 0, nullptr, rps);
    init_out<<<1, 256>>>(out, bfp, S);
    l2norm_final<<<(N + 7) / 8, 256>>>((const float4*)XB, WFP, out, N, rps);
}

// round 17
// speedup vs baseline: 1.1851x; 1.1851x over previous
#include <cuda_runtime.h>
#include <cstdint>

// Problem constants (shapes fixed by the dataset)
#define NN 65536
#define EE 262144

// Scratch (static __device__ arrays; allocation APIs are forbidden)
__device__ float g_XA[(size_t)NN * 512];
__device__ float g_XB[(size_t)NN * 512];
__device__ float g_AG[(size_t)NN * 512];
__device__ float g_WP[192 * 384];       // padded+rounded W1
__device__ float g_WR[1407488];         // rounded copies: W2|Wl0|Wr0|Wl1|Wr1|Wl2|Wr2
__device__ float g_LNS[512];            // 2 buffers x 128 segs x {s1,s2}
__device__ int   g_CNT[NN];
__device__ int   g_OFF[NN + 1];
__device__ int   g_TOPS[64];
__device__ int   g_ADJ[EE];

// offsets into g_WR
#define O_W2  0
#define O_WL0 (O_W2  + 378 * 256)
#define O_WR0 (O_WL0 + 256 * 512)
#define O_WL1 (O_WR0 + 256 * 512)
#define O_WR1 (O_WL1 + 512 * 512)
#define O_WL2 (O_WR1 + 512 * 512)
#define O_WR2 (O_WL2 + 512 * 512)
#define WR_TOTAL (O_WR2 + 512 * 512)

__device__ __forceinline__ float rnd_tf32(float x) {
    uint32_t u;
    asm("cvt.rna.tf32.f32 %0, %1;" : "=r"(u) : "f"(x));
    return __uint_as_float(u);
}

// ---------------------------------------------------------------------------
__global__ void zero_int(int* p, int n) {
    int i = blockIdx.x * blockDim.x + threadIdx.x;
    if (i < n) p[i] = 0;
}
__global__ void zero_f(float* p, int n) {
    int i = blockIdx.x * blockDim.x + threadIdx.x;
    if (i < n) p[i] = 0.f;
}
__global__ void init_out(float* out, const float* bf, int n) {
    int i = blockIdx.x * blockDim.x + threadIdx.x;
    if (i < n) out[i] = bf[0];
}

// Pad W1 [189,378] -> WP [192,384] (zeros elsewhere), tf32-rounded
__global__ void pad_w1(const float* __restrict__ W1, float* __restrict__ WP) {
    int idx = blockIdx.x * blockDim.x + threadIdx.x;
    if (idx >= 192 * 384) return;
    int r = idx / 384, c = idx % 384;
    WP[idx] = (r < 189 && c < 378) ? rnd_tf32(W1[r * 378 + c]) : 0.f;
}

// One kernel rounds all 7 weight matrices into g_WR
__global__ void round_weights(const float* __restrict__ W2,
                              const float* __restrict__ Wl0, const float* __restrict__ Wr0,
                              const float* __restrict__ Wl1, const float* __restrict__ Wr1,
                              const float* __restrict__ Wl2, const float* __restrict__ Wr2,
                              float* __restrict__ WR) {
    int i = blockIdx.x * blockDim.x + threadIdx.x;
    if (i >= WR_TOTAL) return;
    const float* src;
    int off;
    if      (i < O_WL0) { src = W2;  off = O_W2;  }
    else if (i < O_WR0) { src = Wl0; off = O_WL0; }
    else if (i < O_WL1) { src = Wr0; off = O_WR0; }
    else if (i < O_WR1) { src = Wl1; off = O_WL1; }
    else if (i < O_WL2) { src = Wr1; off = O_WR1; }
    else if (i < O_WR2) { src = Wl2; off = O_WL2; }
    else                { src = Wr2; off = O_WR2; }
    WR[i] = rnd_tf32(src[i - off]);
}

// ---------------------------------------------------------------------------
// Build input features x [N,192] = [cat_nf(16)|cat_cf(8)|nf_num(101)|op_emb(64)|pad=0]
__global__ void build_x(const float* __restrict__ nf, const int* __restrict__ ncf,
                        const int* __restrict__ ops, const float* __restrict__ opemb,
                        const float* __restrict__ catemb, float* __restrict__ X) {
    int n = blockIdx.x;
    int c = threadIdx.x;
    if (c >= 192) return;
    float v = 0.f;
    if (c < 16) {
        int f = c >> 2, e = c & 3;
        int cat = (int)nf[(size_t)n * 105 + 101 + f];
        v = catemb[cat * 4 + e];
    } else if (c < 24) {
        int f = (c - 16) >> 2, e = (c - 16) & 3;
        int cat = ncf[n * 2 + f];
        v = catemb[cat * 4 + e];
    } else if (c < 125) {
        v = nf[(size_t)n * 105 + (c - 24)];
    } else if (c < 189) {
        v = opemb[ops[n] * 64 + (c - 125)];
    }
    X[(size_t)n * 192 + c] = rnd_tf32(v);
}

// ---------------------------------------------------------------------------
// CSR build: histogram -> exclusive scan (64 x 1024) -> fill
__global__ void hist_dst(const int* __restrict__ dst, int* __restrict__ cnt, int E) {
    int i = blockIdx.x * blockDim.x + threadIdx.x;
    if (i < E) atomicAdd(&cnt[dst[i]], 1);
}

__global__ void scan1(const int* __restrict__ in, int* __restrict__ out, int* __restrict__ tops) {
    __shared__ int sh[1024];
    int t = threadIdx.x;
    int i = blockIdx.x * 1024 + t;
    int v = in[i];
    sh[t] = v;
    __syncthreads();
    for (int o = 1; o < 1024; o <<= 1) {
        int x = (t >= o) ? sh[t - o] : 0;
        __syncthreads();
        sh[t] += x;
        __syncthreads();
    }
    out[i] = sh[t] - v;
    if (t == 1023) tops[blockIdx.x] = sh[t];
}

__global__ void scan2(int* __restrict__ tops, int* __restrict__ off, int E) {
    __shared__ int sh[64];
    int t = threadIdx.x;
    int v = tops[t];
    sh[t] = v;
    __syncthreads();
    for (int o = 1; o < 64; o <<= 1) {
        int x = (t >= o) ? sh[t - o] : 0;
        __syncthreads();
        sh[t] += x;
        __syncthreads();
    }
    tops[t] = sh[t] - v;
    if (t == 0) off[NN] = E;
}

__global__ void scan3(int* __restrict__ out, const int* __restrict__ tops) {
    out[blockIdx.x * 1024 + threadIdx.x] += tops[blockIdx.x];
}

__global__ void fill_adj(const int* __restrict__ src, const int* __restrict__ dst,
                         const int* __restrict__ off, int* __restrict__ cnt,
                         int* __restrict__ adj, int E) {
    int i = blockIdx.x * blockDim.x + threadIdx.x;
    if (i >= E) return;
    int d = dst[i];
    int p = off[d] + atomicAdd(&cnt[d], 1);
    adj[p] = src[i];
}

// ---------------------------------------------------------------------------
// CSR mean-aggregation: AG[d] = round( sum_{s in adj(d)} X[s] / max(deg,1) )
template <int NQ>
__global__ void aggregate(const float4* __restrict__ X, const int* __restrict__ off,
                          const int* __restrict__ adj, float4* __restrict__ AG) {
    int row = (blockIdx.x * blockDim.x + threadIdx.x) >> 5;
    int lane = threadIdx.x & 31;
    if (row >= NN) return;
    int s0 = off[row], s1 = off[row + 1];
    float4 acc[NQ];
#pragma unroll
    for (int q = 0; q < NQ; q++) acc[q] = make_float4(0.f, 0.f, 0.f, 0.f);
    for (int e = s0; e < s1; e++) {
        int s = adj[e];
        const float4* xr = X + (size_t)s * (NQ * 32);
#pragma unroll
        for (int q = 0; q < NQ; q++) {
            float4 v = xr[lane + 32 * q];
            acc[q].x += v.x; acc[q].y += v.y; acc[q].z += v.z; acc[q].w += v.w;
        }
    }
    float inv = 1.0f / fmaxf((float)(s1 - s0), 1.0f);
    float4* o = AG + (size_t)row * (NQ * 32);
#pragma unroll
    for (int q = 0; q < NQ; q++) {
        float4 u;
        u.x = rnd_tf32(acc[q].x * inv);
        u.y = rnd_tf32(acc[q].y * inv);
        u.z = rnd_tf32(acc[q].z * inv);
        u.w = rnd_tf32(acc[q].w * inv);
        o[lane + 32 * q] = u;
    }
}

// ---------------------------------------------------------------------------
// tf32 tensor-core GEMM (R12 layout), K-concatenated dual input.
// PAIRED pipeline: 3 stages, each holding TWO 16-K subtiles; one
// commit/wait/sync per pair -> half the barriers, 4-tile prefetch distance.
// BM=128, BN=128, 256 threads (8 warps 2x4), 64x32 per warp.
#define PSTAGES 3
#define AS_WORDS (128 * 20)
#define BS_WORDS (16 * 136)
#define SUB_WORDS (AS_WORDS + BS_WORDS)
#define PAIR_WORDS (2 * SUB_WORDS)
#define SMEM_WORDS (PSTAGES * PAIR_WORDS)   // 28416 words = 113664 B

__device__ __forceinline__ void cp_async16(void* smem, const void* gmem, bool pred) {
    uint32_t s = (uint32_t)__cvta_generic_to_shared(smem);
    int sz = pred ? 16 : 0;
    asm volatile("cp.async.cg.shared.global [%0], [%1], 16, %2;\n"
                 :: "r"(s), "l"(gmem), "r"(sz));
}

__device__ __forceinline__ void mma_tf32(float* c, const uint32_t* a, const uint32_t* b) {
    asm volatile(
        "mma.sync.aligned.m16n8k8.row.col.f32.tf32.tf32.f32 "
        "{%0,%1,%2,%3}, {%4,%5,%6,%7}, {%8,%9}, {%0,%1,%2,%3};"
        : "+f"(c[0]), "+f"(c[1]), "+f"(c[2]), "+f"(c[3])
        : "r"(a[0]), "r"(a[1]), "r"(a[2]), "r"(a[3]), "r"(b[0]), "r"(b[1]));
}

__global__ void __launch_bounds__(256, 2)
gemm_tc(const float* __restrict__ A1, const float* __restrict__ B1,
        const float* __restrict__ A2, const float* __restrict__ B2,
        const float* __restrict__ bias, float* __restrict__ C,
        int lda1, int ldb1, int lda2, int ldb2,
        int Mk1, int Mb1, int Mk2, int Mb2,
        int ldc, int Kbias, int act, float* segsum, int rps) {
    extern __shared__ uint32_t dynsmem[];

    const int tid = threadIdx.x;
    const int wid = tid >> 5, lane = tid & 31;
    const int wm = wid & 1, wn = wid >> 1;
    const int g = lane >> 2, t4 = lane & 3;
    const int row0 = blockIdx.y * 128;
    const int col0 = blockIdx.x * 128;

    float acc[4][4][4];
#pragma unroll
    for (int i = 0; i < 4; i++)
#pragma unroll
        for (int j = 0; j < 4; j++)
#pragma unroll
            for (int r = 0; r < 4; r++) acc[i][j][r] = 0.f;

    const int T = (Mk1 + Mk2) >> 4;   // always even for our shapes
    const int P = T >> 1;

    // load one 16-K subtile into the given smem region
    auto load_sub = [&](int t, uint32_t* As, uint32_t* Bs) {
        int k0 = t << 4;
        const float* Ap; const float* Bp; int la, lb, kw, Mb;
        if (k0 < Mk1) { Ap = A1; Bp = B1; la = lda1; lb = ldb1; kw = k0; Mb = Mb1; }
        else          { Ap = A2; Bp = B2; la = lda2; lb = ldb2; kw = k0 - Mk1; Mb = Mb2; }
#pragma unroll
        for (int it = 0; it < 2; it++) {
            int f = tid + it * 256;
            int m = f >> 2, kq = (f & 3) << 2;
            cp_async16(&As[m * 20 + kq], Ap + (size_t)(row0 + m) * la + kw + kq, true);
        }
#pragma unroll
        for (int it = 0; it < 2; it++) {
            int f = tid + it * 256;
            int kr = f >> 5, nq = (f & 31) << 2;
            cp_async16(&Bs[kr * 136 + nq], Bp + (size_t)(kw + kr) * lb + col0 + nq,
                       (kw + kr) < Mb);
        }
    };

    auto issue_pair = [&](int p) {
        uint32_t* base = dynsmem + (p % PSTAGES) * PAIR_WORDS;
        load_sub(2 * p,     base,             base + AS_WORDS);
        load_sub(2 * p + 1, base + SUB_WORDS, base + SUB_WORDS + AS_WORDS);
        asm volatile("cp.async.commit_group;\n" ::: "memory");
    };

    auto compute_sub = [&](const uint32_t* As, const uint32_t* Bs) {
#pragma unroll
        for (int kk = 0; kk < 16; kk += 8) {
            uint32_t af[4][4];
#pragma unroll
            for (int i = 0; i < 4; i++) {
                int m = wm * 64 + i * 16 + g;
                af[i][0] = As[m * 20 + kk + t4];
                af[i][1] = As[(m + 8) * 20 + kk + t4];
                af[i][2] = As[m * 20 + kk + t4 + 4];
                af[i][3] = As[(m + 8) * 20 + kk + t4 + 4];
            }
            uint32_t bfr[4][2];
#pragma unroll
            for (int j = 0; j < 4; j++) {
                int n = wn * 32 + j * 8 + g;
                bfr[j][0] = Bs[(kk + t4) * 136 + n];
                bfr[j][1] = Bs[(kk + t4 + 4) * 136 + n];
            }
#pragma unroll
            for (int i = 0; i < 4; i++)
#pragma unroll
                for (int j = 0; j < 4; j++)
                    mma_tf32(acc[i][j], af[i], bfr[j]);
        }
    };

    issue_pair(0);
    if (P > 1) issue_pair(1);
    for (int p = 0; p < P; p++) {
        if (p + 1 < P) asm volatile("cp.async.wait_group 1;\n" ::: "memory");
        else           asm volatile("cp.async.wait_group 0;\n" ::: "memory");
        __syncthreads();
        if (p + 2 < P) issue_pair(p + 2);
        const uint32_t* base = dynsmem + (p % PSTAGES) * PAIR_WORDS;
        compute_sub(base, base + AS_WORDS);
        compute_sub(base + SUB_WORDS, base + SUB_WORDS + AS_WORDS);
    }
    __syncthreads();

    // epilogue (f32; consumers round on their own writes)
    float ts1 = 0.f, ts2 = 0.f;
#pragma unroll
    for (int i = 0; i < 4; i++) {
        int m = row0 + wm * 64 + i * 16 + g;
#pragma unroll
        for (int j = 0; j < 4; j++) {
            int n = col0 + wn * 32 + j * 8 + t4 * 2;
            float b0 = (n < Kbias) ? bias[n] : 0.f;
            float b1v = (n + 1 < Kbias) ? bias[n + 1] : 0.f;
            float v0 = acc[i][j][0] + b0;
            float v1 = acc[i][j][1] + b1v;
            float v2 = acc[i][j][2] + b0;
            float v3 = acc[i][j][3] + b1v;
            if (act == 1) {
                v0 = v0 >= 0.f ? v0 : 0.01f * v0;
                v1 = v1 >= 0.f ? v1 : 0.01f * v1;
                v2 = v2 >= 0.f ? v2 : 0.01f * v2;
                v3 = v3 >= 0.f ? v3 : 0.01f * v3;
            }
            if (segsum) {
                ts1 += v0 + v1 + v2 + v3;
                ts2 += v0 * v0 + v1 * v1 + v2 * v2 + v3 * v3;
            }
            float2 lo = {v0, v1}, hi = {v2, v3};
            *(float2*)&C[(size_t)m * ldc + n] = lo;
            *(float2*)&C[(size_t)(m + 8) * ldc + n] = hi;
        }
    }

    if (segsum) {
        __shared__ float red[256];
        red[tid] = ts1;
        __syncthreads();
        for (int o = 128; o > 0; o >>= 1) {
            if (tid < o) red[tid] += red[tid + o];
            __syncthreads();
        }
        if (tid == 0) atomicAdd(&segsum[(row0 / rps) * 2], red[0]);
        __syncthreads();
        red[tid] = ts2;
        __syncthreads();
        for (int o = 128; o > 0; o >>= 1) {
            if (tid < o) red[tid] += red[tid + o];
            __syncthreads();
        }
        if (tid == 0) atomicAdd(&segsum[(row0 / rps) * 2 + 1], red[0]);
    }
}

// ---------------------------------------------------------------------------
// Graph-wise LN apply (stats precomputed in GEMM epilogue). float4, 512 thr.
__global__ void graph_ln_apply(float4* __restrict__ X, const float* __restrict__ w,
                               const float* __restrict__ b, const float* __restrict__ segsum,
                               int F, int ld4, int rps) {
    __shared__ float sw[384], sb[384];
    int t = threadIdx.x;
    int cols = ld4 * 4;
    for (int c = t; c < cols; c += 512) {
        sw[c] = (c < F) ? w[c] : 0.f;
        sb[c] = (c < F) ? b[c] : 0.f;
    }
    __syncthreads();
    float cnt = (float)rps * (float)F;
    float mean = segsum[blockIdx.x * 2] / cnt;
    float var = segsum[blockIdx.x * 2 + 1] / cnt - mean * mean;
    float inv = rsqrtf(var + 1e-5f);
    size_t base = (size_t)blockIdx.x * rps * ld4;
    int total = rps * ld4;
    for (int i = t; i < total; i += 512) {
        float4 v = X[base + i];
        int c = (i % ld4) * 4;
        v.x = rnd_tf32((v.x - mean) * inv * sw[c + 0] + sb[c + 0]);
        v.y = rnd_tf32((v.y - mean) * inv * sw[c + 1] + sb[c + 1]);
        v.z = rnd_tf32((v.z - mean) * inv * sw[c + 2] + sb[c + 2]);
        v.w = rnd_tf32((v.w - mean) * inv * sw[c + 3] + sb[c + 3]);
        X[base + i] = v;
    }
}

// ---------------------------------------------------------------------------
// Row L2 normalize (512 cols) + relu + tf32 round. Warp per row.
__global__ void row_l2norm(float4* __restrict__ X, int nrows) {
    int warp = (blockIdx.x * blockDim.x + threadIdx.x) >> 5;
    int lane = threadIdx.x & 31;
    if (warp >= nrows) return;
    float4* row = X + (size_t)warp * 128;
    float4 v[4];
    float ss = 0.f;
#pragma unroll
    for (int k = 0; k < 4; k++) {
        v[k] = row[lane + 32 * k];
        ss += v[k].x * v[k].x + v[k].y * v[k].y + v[k].z * v[k].z + v[k].w * v[k].w;
    }
#pragma unroll
    for (int o = 16; o > 0; o >>= 1) ss += __shfl_xor_sync(0xffffffff, ss, o);
    float s = 1.0f / fmaxf(sqrtf(ss), 1e-12f);
#pragma unroll
    for (int k = 0; k < 4; k++) {
        float4 u = v[k];
        u.x = rnd_tf32(fmaxf(u.x * s, 0.f));
        u.y = rnd_tf32(fmaxf(u.y * s, 0.f));
        u.z = rnd_tf32(fmaxf(u.z * s, 0.f));
        u.w = rnd_tf32(fmaxf(u.w * s, 0.f));
        row[lane + 32 * k] = u;
    }
}

// ---------------------------------------------------------------------------
// Fused last layer: l2-normalize row, dot with Wf, atomicAdd into out[seg].
__global__ void l2norm_final(const float4* __restrict__ X, const float* __restrict__ Wf,
                             float* __restrict__ out, int nrows, int rps) {
    int warp = (blockIdx.x * blockDim.x + threadIdx.x) >> 5;
    int lane = threadIdx.x & 31;
    if (warp >= nrows) return;
    const float4* row = X + (size_t)warp * 128;
    const float4* wf4 = (const float4*)Wf;
    float ss = 0.f, dot = 0.f;
#pragma unroll
    for (int k = 0; k < 4; k++) {
        float4 v = row[lane + 32 * k];
        float4 w = wf4[lane + 32 * k];
        ss += v.x * v.x + v.y * v.y + v.z * v.z + v.w * v.w;
        dot += v.x * w.x + v.y * w.y + v.z * w.z + v.w * w.w;
    }
#pragma unroll
    for (int o = 16; o > 0; o >>= 1) {
        ss += __shfl_xor_sync(0xffffffff, ss, o);
        dot += __shfl_xor_sync(0xffffffff, dot, o);
    }
    if (lane == 0) {
        float s = 1.0f / fmaxf(sqrtf(ss), 1e-12f);
        atomicAdd(&out[warp / rps], dot * s);
    }
}

// ---------------------------------------------------------------------------
extern "C" void kernel_launch(void* const* d_in, const int* in_sizes, int n_in,
                              void* d_out, int out_size) {
    const float* nf    = (const float*)d_in[0];
    const int*   ncf   = (const int*)d_in[1];
    const int*   ops   = (const int*)d_in[3];
    const int*   edges = (const int*)d_in[4];
    const float* opemb = (const float*)d_in[6];
    const float* catemb= (const float*)d_in[7];
    const float* W1    = (const float*)d_in[8];
    const float* b1    = (const float*)d_in[9];
    const float* ln1w  = (const float*)d_in[10];
    const float* ln1b  = (const float*)d_in[11];
    const float* W2    = (const float*)d_in[12];
    const float* b2    = (const float*)d_in[13];
    const float* ln2w  = (const float*)d_in[14];
    const float* ln2b  = (const float*)d_in[15];
    const float* Wl0   = (const float*)d_in[16];
    const float* bl0   = (const float*)d_in[17];
    const float* Wr0   = (const float*)d_in[18];
    const float* Wl1   = (const float*)d_in[19];
    const float* bl1   = (const float*)d_in[20];
    const float* Wr1   = (const float*)d_in[21];
    const float* Wl2   = (const float*)d_in[22];
    const float* bl2   = (const float*)d_in[23];
    const float* Wr2   = (const float*)d_in[24];
    const float* Wf    = (const float*)d_in[25];
    const float* bfp   = (const float*)d_in[26];
    float* out = (float*)d_out;

    const int N = in_sizes[3];
    const int S = in_sizes[2];
    const int E = in_sizes[4] / 2;
    const int rps = N / S;
    const int* esrc = edges;
    const int* edst = edges + E;

    float *XA, *XB, *AG, *WP, *WR, *LNS;
    int *CNT, *OFF, *TOPS, *ADJ;
    cudaGetSymbolAddress((void**)&XA, g_XA);
    cudaGetSymbolAddress((void**)&XB, g_XB);
    cudaGetSymbolAddress((void**)&AG, g_AG);
    cudaGetSymbolAddress((void**)&WP, g_WP);
    cudaGetSymbolAddress((void**)&WR, g_WR);
    cudaGetSymbolAddress((void**)&LNS, g_LNS);
    cudaGetSymbolAddress((void**)&CNT, g_CNT);
    cudaGetSymbolAddress((void**)&OFF, g_OFF);
    cudaGetSymbolAddress((void**)&TOPS, g_TOPS);
    cudaGetSymbolAddress((void**)&ADJ, g_ADJ);

    const int gy = N / 128;
    const int smem_bytes = SMEM_WORDS * 4;   // 113664
    cudaFuncSetAttribute(gemm_tc, cudaFuncAttributeMaxDynamicSharedMemorySize, smem_bytes);

    // 1. W1 pad+round
    pad_w1<<<(192 * 384 + 255) / 256, 256>>>(W1, WP);
    // 2. zero LN stats
    zero_f<<<2, 256>>>(LNS, 512);
    // 3. feature assembly -> AG used as X1 [N,192]
    build_x<<<N, 192>>>(nf, ncf, ops, opemb, catemb, AG);
    // 4. XB = LN-stats(leaky(X1 @ W1 + b1))  [N,378] stride 384   << profiled
    gemm_tc<<<dim3(3, gy), 256, smem_bytes>>>(AG, WP, AG, WP, b1, XB,
                                              192, 384, 192, 384,
                                              192, 192, 0, 0,
                                              384, 378, 1, LNS, rps);
    // 5. LN apply
    graph_ln_apply<<<S, 512>>>((float4*)XB, ln1w, ln1b, LNS, 378, 96, rps);
    // 6. remaining weight rounds
    round_weights<<<(WR_TOTAL + 255) / 256, 256>>>(W2, Wl0, Wr0, Wl1, Wr1, Wl2, Wr2, WR);

    // 7. XA = LN(leaky(XB @ W2 + b2))  [N,256]; stats fused
    gemm_tc<<<dim3(2, gy), 256, smem_bytes>>>(XB, WR + O_W2, XB, WR + O_W2, b2, XA,
                                              384, 256, 384, 256,
                                              384, 378, 0, 0,
                                              256, 256, 1, LNS + 256, rps);
    graph_ln_apply<<<S, 512>>>((float4*)XA, ln2w, ln2b, LNS + 256, 256, 64, rps);

    // CSR build (needed before first aggregate)
    zero_int<<<N / 256, 256>>>(CNT, N);
    hist_dst<<<(E + 255) / 256, 256>>>(edst, CNT, E);
    scan1<<<64, 1024>>>(CNT, OFF, TOPS);
    scan2<<<1, 64>>>(TOPS, OFF, E);
    scan3<<<64, 1024>>>(OFF, TOPS);
    zero_int<<<N / 256, 256>>>(CNT, N);
    fill_adj<<<(E + 255) / 256, 256>>>(esrc, edst, OFF, CNT, ADJ, E);

    // SAGE layer 0: 256 -> 512, relu(l2norm)
    aggregate<2><<<N / 8, 256>>>((const float4*)XA, OFF, ADJ, (float4*)AG);
    gemm_tc<<<dim3(4, gy), 256, smem_bytes>>>(AG, WR + O_WL0, XA, WR + O_WR0, bl0, XB,
                                              256, 512, 256, 512,
                                              256, 256, 256, 256,
                                              512, 512, 0, nullptr, rps);
    row_l2norm<<<(N + 7) / 8, 256>>>((float4*)XB, N);

    // SAGE layer 1: 512 -> 512, relu(l2norm)
    aggregate<4><<<N / 8, 256>>>((const float4*)XB, OFF, ADJ, (float4*)AG);
    gemm_tc<<<dim3(4, gy), 256, smem_bytes>>>(AG, WR + O_WL1, XB, WR + O_WR1, bl1, XA,
                                              512, 512, 512, 512,
                                              512, 512, 512, 512,
                                              512, 512, 0, nullptr, rps);
    row_l2norm<<<(N + 7) / 8, 256>>>((float4*)XA, N);

    // SAGE layer 2: 512 -> 512, fused l2norm+dot+segment-reduce
    aggregate<4><<<N / 8, 256>>>((const float4*)XA, OFF, ADJ, (float4*)AG);
    gemm_tc<<<dim3(4, gy), 256, smem_bytes>>>(AG, WR + O_WL2, XA, WR + O_WR2, bl2, XB,
                                              512, 512, 512, 512,
                                              512, 512, 512, 512,
                                              512, 512, 0, nullptr, rps);
    init_out<<<1, 256>>>(out, bfp, S);
    l2norm_final<<<(N + 7) / 8, 256>>>((const float4*)XB, Wf, out, N, rps);
}